// round 2
// baseline (speedup 1.0000x reference)
#include <cuda_runtime.h>
#include <math.h>

#define BATCH 8
#define CCH   256
#define DD    32
#define NN    4096
#define BM    64
#define BN    64
#define PT_STRIDE 68
#define VS_STRIDE 68

// Scratch for q/k/v projections (allocation-free rule: __device__ globals)
__device__ float g_q[BATCH * DD * NN];     // [b][d][n]
__device__ float g_k[BATCH * DD * NN];     // [b][d][n]
__device__ float g_v[BATCH * CCH * NN];    // [b][c][n]

// ---------------------------------------------------------------------------
// Projection GEMM: out[b][r][n] = sum_c W[r][c] * x[b][c][n] + bias[r]
// Tile: 32 rows x 128 cols, K chunks of 32 over C=256. 256 threads.
// ---------------------------------------------------------------------------
__global__ __launch_bounds__(256) void proj_kernel(
    const float* __restrict__ W, const float* __restrict__ bias,
    const float* __restrict__ x, float* __restrict__ out, int R)
{
    __shared__ float Ws[32 * 33];     // [r][c], pad 1
    __shared__ float Xs[32 * 132];    // [c][n], pad 4 (float4 aligned)

    const int b  = blockIdx.z;
    const int r0 = blockIdx.y * 32;
    const int n0 = blockIdx.x * 128;
    const int tid = threadIdx.x;
    const int ty = tid >> 5;          // 0..7  (warp id; uniform per warp)
    const int tx = tid & 31;

    const float* xb = x + (size_t)b * CCH * NN;
    float* ob = out + (size_t)b * R * NN;

    float acc[4][4];
    #pragma unroll
    for (int r = 0; r < 4; r++) {
        float bv = bias[r0 + ty * 4 + r];
        acc[r][0] = bv; acc[r][1] = bv; acc[r][2] = bv; acc[r][3] = bv;
    }

    for (int c0 = 0; c0 < CCH; c0 += 32) {
        __syncthreads();
        // Ws: 32x32, coalesced along c; shared stride 33 -> conflict-free
        for (int i = tid; i < 32 * 32; i += 256) {
            int r = i >> 5, c = i & 31;
            Ws[r * 33 + c] = W[(size_t)(r0 + r) * CCH + c0 + c];
        }
        // Xs: 32 c-rows x 128 n, float4 loads, coalesced along n
        for (int i = tid; i < 32 * 32; i += 256) {
            int c = i >> 5, nq = i & 31;
            *(float4*)&Xs[c * 132 + nq * 4] =
                *(const float4*)&xb[(size_t)(c0 + c) * NN + n0 + nq * 4];
        }
        __syncthreads();

        #pragma unroll 8
        for (int kk = 0; kk < 32; kk++) {
            float4 xv = *(const float4*)&Xs[kk * 132 + tx * 4];
            #pragma unroll
            for (int r = 0; r < 4; r++) {
                float wv = Ws[(ty * 4 + r) * 33 + kk];   // warp-broadcast
                acc[r][0] += wv * xv.x;
                acc[r][1] += wv * xv.y;
                acc[r][2] += wv * xv.z;
                acc[r][3] += wv * xv.w;
            }
        }
    }

    #pragma unroll
    for (int r = 0; r < 4; r++) {
        float4 o = make_float4(acc[r][0], acc[r][1], acc[r][2], acc[r][3]);
        *(float4*)&ob[(size_t)(r0 + ty * 4 + r) * NN + n0 + tx * 4] = o;
    }
}

// ---------------------------------------------------------------------------
// Flash attention + fused epilogue:
//   out[b][c][n] = gamma * (sum_m softmax_m(q_n . k_m) * v[c][m]) + x[b][c][n]
// Block: BM=64 queries, loop key tiles of BN=64. 256 threads.
// Thread (lane, warp w): queries {lane, lane+32}, channels [32w, 32w+32).
// ---------------------------------------------------------------------------
__global__ __launch_bounds__(256, 2) void attn_kernel(
    const float* __restrict__ x, const float* __restrict__ gammap,
    float* __restrict__ out)
{
    extern __shared__ float sm[];
    float* Qs = sm;                       // [DD][BM]      2048
    float* Ks = Qs + DD * BM;             // [DD][BN]      2048
    float* Pt = Ks + DD * BN;             // [BN][68]      4352  (transposed scores)
    float* Vs = Pt + BN * PT_STRIDE;      // [CCH][68]    17408  (c-major)
    float* row_m   = Vs + CCH * VS_STRIDE;   // [BM]
    float* row_l   = row_m + BM;             // [BM]
    float* alpha_s = row_l + BM;             // [BM]

    const int b  = blockIdx.y;
    const int q0 = blockIdx.x * BM;
    const int tid  = threadIdx.x;
    const int lane = tid & 31;
    const int w    = tid >> 5;

    const float* qb = g_q + (size_t)b * DD * NN;
    const float* kb = g_k + (size_t)b * DD * NN;
    const float* vb = g_v + (size_t)b * CCH * NN;

    // Load Q tile (Qs[d][q]); coalesced global, conflict-free shared
    for (int i = tid; i < DD * BM; i += 256) {
        int d = i >> 6, q = i & 63;
        Qs[d * BM + q] = qb[(size_t)d * NN + q0 + q];
    }
    if (tid < BM) { row_m[tid] = -1e30f; row_l[tid] = 0.0f; }

    float acc[2][32];
    #pragma unroll
    for (int qi = 0; qi < 2; qi++)
        #pragma unroll
        for (int cc = 0; cc < 32; cc++) acc[qi][cc] = 0.0f;
    __syncthreads();

    const int sq = tid & 63;            // score-phase query
    const int j0 = (tid >> 6) * 16;     // score-phase key group (warp-uniform)
    const int cbase = w * 32;

    for (int m0 = 0; m0 < NN; m0 += BN) {
        // --- load K tile Ks[d][j] ---
        for (int i = tid; i < DD * BN; i += 256) {
            int d = i >> 6, j = i & 63;
            Ks[d * BN + j] = kb[(size_t)d * NN + m0 + j];
        }
        // --- load V tile Vs[c][j] via float4 ---
        for (int i = tid; i < CCH * (BN / 4); i += 256) {
            int c = i >> 4, jq = i & 15;
            *(float4*)&Vs[c * VS_STRIDE + jq * 4] =
                *(const float4*)&vb[(size_t)c * NN + m0 + jq * 4];
        }
        __syncthreads();

        // --- scores: S[q][j] = sum_d Q[d][q] * K[d][j], 16 j per thread ---
        float sreg[16];
        #pragma unroll
        for (int jj = 0; jj < 16; jj++) sreg[jj] = 0.0f;
        #pragma unroll 8
        for (int d = 0; d < DD; d++) {
            float qv = Qs[d * BM + sq];
            const float4* kr = (const float4*)&Ks[d * BN + j0];
            float4 k0 = kr[0], k1 = kr[1], k2 = kr[2], k3 = kr[3];
            sreg[0]  += qv * k0.x; sreg[1]  += qv * k0.y;
            sreg[2]  += qv * k0.z; sreg[3]  += qv * k0.w;
            sreg[4]  += qv * k1.x; sreg[5]  += qv * k1.y;
            sreg[6]  += qv * k1.z; sreg[7]  += qv * k1.w;
            sreg[8]  += qv * k2.x; sreg[9]  += qv * k2.y;
            sreg[10] += qv * k2.z; sreg[11] += qv * k2.w;
            sreg[12] += qv * k3.x; sreg[13] += qv * k3.y;
            sreg[14] += qv * k3.z; sreg[15] += qv * k3.w;
        }
        #pragma unroll
        for (int jj = 0; jj < 16; jj++)
            Pt[(j0 + jj) * PT_STRIDE + sq] = sreg[jj];
        __syncthreads();

        // --- online softmax (one thread per query row) ---
        if (tid < BM) {
            const int q = tid;
            float mold = row_m[q];
            float mnew = mold;
            #pragma unroll 8
            for (int j = 0; j < BN; j++)
                mnew = fmaxf(mnew, Pt[j * PT_STRIDE + q]);
            float al = __expf(mold - mnew);
            float l  = row_l[q] * al;
            #pragma unroll 8
            for (int j = 0; j < BN; j++) {
                float p = __expf(Pt[j * PT_STRIDE + q] - mnew);
                Pt[j * PT_STRIDE + q] = p;
                l += p;
            }
            row_m[q] = mnew; row_l[q] = l; alpha_s[q] = al;
        }
        __syncthreads();

        // --- rescale + PV accumulate ---
        float a0 = alpha_s[lane], a1 = alpha_s[lane + 32];
        #pragma unroll
        for (int cc = 0; cc < 32; cc++) { acc[0][cc] *= a0; acc[1][cc] *= a1; }

        #pragma unroll 2
        for (int jq = 0; jq < BN; jq += 4) {
            float p0a = Pt[(jq + 0) * PT_STRIDE + lane];
            float p1a = Pt[(jq + 1) * PT_STRIDE + lane];
            float p2a = Pt[(jq + 2) * PT_STRIDE + lane];
            float p3a = Pt[(jq + 3) * PT_STRIDE + lane];
            float p0b = Pt[(jq + 0) * PT_STRIDE + lane + 32];
            float p1b = Pt[(jq + 1) * PT_STRIDE + lane + 32];
            float p2b = Pt[(jq + 2) * PT_STRIDE + lane + 32];
            float p3b = Pt[(jq + 3) * PT_STRIDE + lane + 32];
            #pragma unroll
            for (int cc = 0; cc < 32; cc++) {
                float4 vv = *(const float4*)&Vs[(cbase + cc) * VS_STRIDE + jq];
                acc[0][cc] += p0a * vv.x + p1a * vv.y + p2a * vv.z + p3a * vv.w;
                acc[1][cc] += p0b * vv.x + p1b * vv.y + p2b * vv.z + p3b * vv.w;
            }
        }
        __syncthreads();
    }

    // --- epilogue: out = gamma * acc / l + x, coalesced along n ---
    const float g = gammap[0];
    const float inva = g / row_l[lane];
    const float invb = g / row_l[lane + 32];
    const float* xb = x + (size_t)b * CCH * NN;
    float* ob = out + (size_t)b * CCH * NN;
    #pragma unroll
    for (int cc = 0; cc < 32; cc++) {
        size_t base = (size_t)(cbase + cc) * NN + q0;
        ob[base + lane]      = acc[0][cc] * inva + xb[base + lane];
        ob[base + lane + 32] = acc[1][cc] * invb + xb[base + lane + 32];
    }
}

// ---------------------------------------------------------------------------
extern "C" void kernel_launch(void* const* d_in, const int* in_sizes, int n_in,
                              void* d_out, int out_size)
{
    const float* x     = (const float*)d_in[0];
    const float* wq    = (const float*)d_in[1];
    const float* bq    = (const float*)d_in[2];
    const float* wk    = (const float*)d_in[3];
    const float* bk    = (const float*)d_in[4];
    const float* wv    = (const float*)d_in[5];
    const float* bv    = (const float*)d_in[6];
    const float* gamma = (const float*)d_in[7];
    float* out = (float*)d_out;

    float *qptr, *kptr, *vptr;
    cudaGetSymbolAddress((void**)&qptr, g_q);
    cudaGetSymbolAddress((void**)&kptr, g_k);
    cudaGetSymbolAddress((void**)&vptr, g_v);

    dim3 gqk(NN / 128, DD / 32, BATCH);
    proj_kernel<<<gqk, 256>>>(wq, bq, x, qptr, DD);
    proj_kernel<<<gqk, 256>>>(wk, bk, x, kptr, DD);
    dim3 gv(NN / 128, CCH / 32, BATCH);
    proj_kernel<<<gv, 256>>>(wv, bv, x, vptr, CCH);

    const size_t smem = (size_t)(DD * BM + DD * BN + BN * PT_STRIDE +
                                 CCH * VS_STRIDE + 3 * BM) * sizeof(float);
    cudaFuncSetAttribute(attn_kernel,
                         cudaFuncAttributeMaxDynamicSharedMemorySize, (int)smem);
    dim3 ga(NN / BM, BATCH);
    attn_kernel<<<ga, 256, smem>>>(x, gamma, out);
}